// round 1
// baseline (speedup 1.0000x reference)
#include <cuda_runtime.h>
#include <math.h>

// ---------------- problem constants ----------------
// SPARSE_SHAPE=(468,468,1), WINDOW=(12,12,1), BATCH=4
// _NX=_NY=40, _NZ=2, per_sample=3200, NUM_WINDOWS=12800
#define WNUM 12800
#define TILE 1024
#define MAXN 310016
#define MAXT ((MAXN + TILE - 1) / TILE)

// ---------------- static scratch (no allocation allowed) ----------------
__device__ int g_win0[MAXN];
__device__ int g_win1[MAXN];
__device__ int g_rank0[MAXN];
__device__ int g_rank1[MAXN];
__device__ unsigned g_cw[MAXN];          // packed in-window coords: x0|y0<<8|x1<<16|y1<<24
__device__ unsigned char g_keep1[MAXN];  // keep after drop pass 0
__device__ unsigned char g_keepF[MAXN];  // final keep
__device__ int g_hist[(long)MAXT * WNUM];
__device__ int g_counts0[WNUM];
__device__ int g_counts1[WNUM];

__device__ __forceinline__ void level_target(int n, int& lvl, int& tgt) {
    if (n < 16)      { lvl = 0; tgt = 16; }
    else if (n < 32) { lvl = 1; tgt = 32; }
    else if (n < 64) { lvl = 2; tgt = 64; }
    else             { lvl = 3; tgt = 144; }
}

// ---------------- kernels ----------------

__global__ void k_prepare(const int* __restrict__ coords, int N) {
    int i = blockIdx.x * blockDim.x + threadIdx.x;
    if (i >= N) return;
    int b = coords[4 * i + 0];
    int z = coords[4 * i + 1];
    int y = coords[4 * i + 2];
    int x = coords[4 * i + 3];
    // do_shift=False: sx=sy=12, sz=0 (SPARSE_SHAPE[2]==wz)
    int cx0 = x + 12, cy0 = y + 12;
    // do_shift=True: sx=sy=6, sz=0
    int cx1 = x + 6, cy1 = y + 6;
    // win = b*3200 + winx*(_NY*_NZ=80) + winy*_NZ(=2) + winz(= z//1 = z)
    g_win0[i] = b * 3200 + (cx0 / 12) * 80 + (cy0 / 12) * 2 + z;
    g_win1[i] = b * 3200 + (cx1 / 12) * 80 + (cy1 / 12) * 2 + z;
    g_cw[i] = (unsigned)(cx0 % 12) | ((unsigned)(cy0 % 12) << 8) |
              ((unsigned)(cx1 % 12) << 16) | ((unsigned)(cy1 % 12) << 24);
}

template <int PASS>
__global__ void k_hist(int N) {
    int t = blockIdx.x;
    int* row = g_hist + (long)t * WNUM;
    for (int j = threadIdx.x; j < WNUM; j += blockDim.x) row[j] = 0;
    __syncthreads();
    int start = t * TILE;
    int end = min(start + TILE, N);
    const int* win = (PASS == 0) ? g_win0 : g_win1;
    for (int i = start + threadIdx.x; i < end; i += blockDim.x) {
        if (PASS == 0 || g_keep1[i]) atomicAdd(&row[win[i]], 1);
    }
}

template <int PASS>
__global__ void k_scan(int T) {
    int w = blockIdx.x * blockDim.x + threadIdx.x;
    if (w >= WNUM) return;
    int run = 0;
    for (int t = 0; t < T; t++) {
        long idx = (long)t * WNUM + w;
        int v = g_hist[idx];
        g_hist[idx] = run;   // exclusive-over-tiles prefix for window w
        run += v;
    }
    ((PASS == 0) ? g_counts0 : g_counts1)[w] = run;
}

// One warp per tile. Stable rank: rank[i] = #(j<i, same window, kept).
template <int PASS>
__global__ void k_rank(int N) {
    int t = blockIdx.x;
    int lane = threadIdx.x;  // blockDim = 32
    int* row = g_hist + (long)t * WNUM;  // running per-window counters (starts at scanned prefix)
    const int* win = (PASS == 0) ? g_win0 : g_win1;
    int* rank = (PASS == 0) ? g_rank0 : g_rank1;
    int start = t * TILE;
    int end = min(start + TILE, N);
    for (int base = start; base < end; base += 32) {
        int i = base + lane;
        bool valid = (i < end) && (PASS == 0 || g_keep1[i]);
        int w = valid ? win[i] : (WNUM + lane);  // unique sentinel per invalid lane
        unsigned peers = __match_any_sync(0xffffffffu, w);
        int leader = __ffs(peers) - 1;
        int r = __popc(peers & ((1u << lane) - 1u));
        int basec = 0;
        if (valid && lane == leader) {
            basec = row[w];
            row[w] = basec + __popc(peers);  // distinct w per group -> no conflict
        }
        basec = __shfl_sync(0xffffffffu, basec, leader);
        if (valid) rank[i] = basec + r;
    }
}

__global__ void k_keep1(int N) {
    int i = blockIdx.x * blockDim.x + threadIdx.x;
    if (i >= N) return;
    int lvl, tgt;
    level_target(g_counts0[g_win0[i]], lvl, tgt);
    g_keep1[i] = (g_rank0[i] < tgt) ? 1 : 0;
}

// Scalar outputs: keep, win0, win1, dl0, dl1, inner0, inner1 (all as float)
__global__ void k_scalars(float* __restrict__ out, int N) {
    int i = blockIdx.x * blockDim.x + threadIdx.x;
    if (i >= N) return;
    long Nl = N;
    int w0 = g_win0[i], w1 = g_win1[i], r0 = g_rank0[i];
    int lvl0, t0;
    level_target(g_counts0[w0], lvl0, t0);
    bool keep1 = r0 < t0;
    int lvl1 = -1, r1o = -1;
    bool keepF = false;
    if (keep1) {
        int r1 = g_rank1[i];
        int tg;
        level_target(g_counts1[w1], lvl1, tg);
        r1o = r1;
        keepF = r1 < tg;
    }
    g_keepF[i] = keepF ? 1 : 0;
    out[128 * Nl + i] = keepF ? 1.0f : 0.0f;
    out[129 * Nl + i] = (float)w0;
    out[130 * Nl + i] = (float)w1;
    out[131 * Nl + i] = (float)lvl0;
    out[132 * Nl + i] = (float)lvl1;
    out[133 * Nl + i] = (float)r0;
    out[134 * Nl + i] = (float)r1o;
}

// Streaming kernel: feat_kept (masked copy), pe0, pe1 from a 12x64 shared LUT.
// One warp per token; each lane handles 4 consecutive floats.
template <bool VEC4>
__global__ void k_vec(const float* __restrict__ feat, float* __restrict__ out, int N) {
    __shared__ float tab[12 * 64];  // tab[v][2i]=sin((v-6)/f_i), tab[v][2i+1]=cos
    for (int j = threadIdx.x; j < 12 * 32; j += blockDim.x) {
        int v = j >> 5;
        int fi = j & 31;
        // inv_freq = 10000^(fi/32); ln(10000)/32 = 0.28782313662425575
        double inv = exp((double)fi * 0.28782313662425575);
        float arg = (float)(((double)(v - 6)) / inv);
        float s, c;
        sincosf(arg, &s, &c);
        tab[v * 64 + 2 * fi]     = s;
        tab[v * 64 + 2 * fi + 1] = c;
    }
    __syncthreads();

    int warp = threadIdx.x >> 5;
    int lane = threadIdx.x & 31;
    int tok = blockIdx.x * (blockDim.x >> 5) + warp;
    if (tok >= N) return;

    unsigned cw = g_cw[tok];
    bool kf = g_keepF[tok] != 0;
    long Nl = N;
    int half = lane >> 4;  // 0: x-half (cols 0..63), 1: y-half (cols 64..127)
    int v0 = half ? ((cw >> 8) & 255) : (cw & 255);
    int v1 = half ? ((cw >> 24) & 255) : ((cw >> 16) & 255);

    if (VEC4) {
        int col = lane & 15;
        float4 f = ((const float4*)feat)[(long)tok * 32 + lane];
        if (!kf) { f.x = 0.f; f.y = 0.f; f.z = 0.f; f.w = 0.f; }
        ((float4*)out)[(long)tok * 32 + lane] = f;
        const float4* tab4 = (const float4*)tab;
        float4 p0 = tab4[v0 * 16 + col];
        float4 p1 = tab4[v1 * 16 + col];
        ((float4*)(out + 135 * Nl))[(long)tok * 32 + lane] = p0;
        ((float4*)(out + 263 * Nl))[(long)tok * 32 + lane] = p1;
    } else {
#pragma unroll
        for (int k = 0; k < 4; k++) {
            int c = lane * 4 + k;
            float f = feat[(long)tok * 128 + c];
            out[(long)tok * 128 + c] = kf ? f : 0.f;
            int cc = c & 63;
            out[135 * Nl + (long)tok * 128 + c] = tab[v0 * 64 + cc];
            out[263 * Nl + (long)tok * 128 + c] = tab[v1 * 64 + cc];
        }
    }
}

// ---------------- launch ----------------
extern "C" void kernel_launch(void* const* d_in, const int* in_sizes, int n_in,
                              void* d_out, int out_size) {
    const float* feat = (const float*)d_in[0];
    const int* coords = (const int*)d_in[1];
    float* out = (float*)d_out;
    int N = in_sizes[1] / 4;
    if (N > MAXN) N = MAXN;
    int T = (N + TILE - 1) / TILE;
    int nb = (N + 255) / 256;

    k_prepare<<<nb, 256>>>(coords, N);

    // drop pass 0 (all tokens kept)
    k_hist<0><<<T, 256>>>(N);
    k_scan<0><<<(WNUM + 255) / 256, 256>>>(T);
    k_rank<0><<<T, 32>>>(N);
    k_keep1<<<nb, 256>>>(N);

    // drop pass 1 (shifted windows, kept tokens only)
    k_hist<1><<<T, 256>>>(N);
    k_scan<1><<<(WNUM + 255) / 256, 256>>>(T);
    k_rank<1><<<T, 32>>>(N);

    k_scalars<<<nb, 256>>>(out, N);

    int vb = (N + 7) / 8;  // 8 warps (tokens) per 256-thread block
    if ((N & 3) == 0) k_vec<true><<<vb, 256>>>(feat, out, N);
    else              k_vec<false><<<vb, 256>>>(feat, out, N);
}

// round 2
// speedup vs baseline: 3.7187x; 3.7187x over previous
#include <cuda_runtime.h>
#include <math.h>

// ---------------- problem constants ----------------
// SPARSE_SHAPE=(468,468,1), WINDOW=(12,12,1), BATCH=4
// _NX=_NY=40, _NZ=2, per_sample=3200, NUM_WINDOWS=12800
// window id = b*3200 + winx*80 + winy*2 + z  -- already in [0, 12800)
#define WNUM 12800
#define MAXN 310016
#define NT 148          // one rank tile per SM
#define MAXT 160

// ---------------- static scratch ----------------
__device__ int g_win0[MAXN];
__device__ int g_win1[MAXN];
__device__ int g_rank0[MAXN];
__device__ int g_rank1[MAXN];
__device__ unsigned g_cw[MAXN];          // packed coords: x0|y0<<8|x1<<16|y1<<24
__device__ unsigned char g_keep1[MAXN];
__device__ unsigned char g_keepF[MAXN];
__device__ int g_hist[(long)MAXT * WNUM];   // tile-major: [t][w]
__device__ int g_counts0[WNUM];
__device__ int g_counts1[WNUM];
__device__ float g_tab[12 * 64];            // sincos LUT, built once

__device__ __forceinline__ void level_target(int n, int& lvl, int& tgt) {
    if (n < 16)      { lvl = 0; tgt = 16; }
    else if (n < 32) { lvl = 1; tgt = 32; }
    else if (n < 64) { lvl = 2; tgt = 64; }
    else             { lvl = 3; tgt = 144; }
}

// ---------------- kernels ----------------

__global__ void k_table() {
    int j = threadIdx.x;
    if (j >= 384) return;
    int v = j >> 5;
    int fi = j & 31;
    // inv_freq = 10000^(fi/32); ln(10000)/32 = 0.28782313662425575
    double inv = exp((double)fi * 0.28782313662425575);
    float arg = (float)(((double)(v - 6)) / inv);
    float s, c;
    sincosf(arg, &s, &c);
    g_tab[v * 64 + 2 * fi]     = s;
    g_tab[v * 64 + 2 * fi + 1] = c;
}

__global__ void k_prepare(const int* __restrict__ coords, int N) {
    int i = blockIdx.x * blockDim.x + threadIdx.x;
    if (i >= N) return;
    int b = coords[4 * i + 0];
    int z = coords[4 * i + 1];
    int y = coords[4 * i + 2];
    int x = coords[4 * i + 3];
    int cx0 = x + 12, cy0 = y + 12;   // do_shift=False (sz=0)
    int cx1 = x + 6,  cy1 = y + 6;    // do_shift=True  (sz=0)
    g_win0[i] = b * 3200 + (cx0 / 12) * 80 + (cy0 / 12) * 2 + z;
    g_win1[i] = b * 3200 + (cx1 / 12) * 80 + (cy1 / 12) * 2 + z;
    g_cw[i] = (unsigned)(cx0 % 12) | ((unsigned)(cy0 % 12) << 8) |
              ((unsigned)(cx1 % 12) << 16) | ((unsigned)(cy1 % 12) << 24);
}

// Per-tile stable rank + per-tile histogram, all in shared memory.
// Block t handles tokens [t*TILE, t*TILE+len). Warp 0 does the ordered walk;
// all 256 threads stage inputs and dump the histogram (coalesced).
template <int PASS>
__global__ void __launch_bounds__(256) k_rankhist(int N, int TILE) {
    extern __shared__ int sh[];
    int* cnt = sh;                               // WNUM ints
    int tilepad = (TILE + 15) & ~15;
    int* swin = sh + WNUM;                       // tilepad ints
    unsigned char* skeep = (unsigned char*)(swin + tilepad);
    int t = blockIdx.x, tid = threadIdx.x;
    int start = t * TILE;
    int len = min(TILE, N - start);
    if (len < 0) len = 0;
    const int* win = (PASS == 0) ? g_win0 : g_win1;

    for (int j = tid; j < WNUM; j += 256) cnt[j] = 0;
    for (int j = tid; j < len; j += 256) swin[j] = win[start + j];
    if (PASS == 1)
        for (int j = tid; j < len; j += 256) skeep[j] = g_keep1[start + j];
    __syncthreads();

    if (tid < 32) {
        int lane = tid;
        int* rank = (PASS == 0) ? g_rank0 : g_rank1;
        for (int base = 0; base < len; base += 32) {
            int j = base + lane;
            bool inb = j < len;
            bool valid = inb && (PASS == 0 || skeep[j]);
            int w = valid ? swin[j] : (WNUM + lane);  // unique sentinel per lane
            unsigned peers = __match_any_sync(0xffffffffu, w);
            int leader = __ffs(peers) - 1;
            int r = __popc(peers & ((1u << lane) - 1u));
            int basec = 0;
            if (valid && lane == leader) {
                basec = cnt[w];
                cnt[w] = basec + __popc(peers);  // distinct w per group
            }
            basec = __shfl_sync(0xffffffffu, basec, leader);
            if (inb) rank[start + j] = valid ? (basec + r) : 0;
            __syncwarp();  // make cnt[] updates visible to next batch
        }
    }
    __syncthreads();

    int* hrow = g_hist + (long)t * WNUM;
    for (int j = tid; j < WNUM; j += 256) hrow[j] = cnt[j];
}

// Exclusive prefix over tiles per window (tile-major => coalesced),
// software-pipelined for MLP. Also emits per-window totals.
template <int PASS>
__global__ void k_scan(int T) {
    int w = blockIdx.x * blockDim.x + threadIdx.x;
    if (w >= WNUM) return;
    int* p = g_hist + w;
    int run = 0, t = 0;
    for (; t + 8 <= T; t += 8) {
        int v[8];
#pragma unroll
        for (int k = 0; k < 8; k++) v[k] = p[(long)(t + k) * WNUM];
#pragma unroll
        for (int k = 0; k < 8; k++) { p[(long)(t + k) * WNUM] = run; run += v[k]; }
    }
    for (; t < T; t++) { int v = p[(long)t * WNUM]; p[(long)t * WNUM] = run; run += v; }
    ((PASS == 0) ? g_counts0 : g_counts1)[w] = run;
}

// Fix up rank0 with tile prefix, decide keep after drop pass 0.
__global__ void k_keep1(int N, int TILE) {
    int i = blockIdx.x * blockDim.x + threadIdx.x;
    if (i >= N) return;
    int w = g_win0[i];
    int t = i / TILE;
    int r = g_rank0[i] + g_hist[(long)t * WNUM + w];
    g_rank0[i] = r;
    int lvl, tgt;
    level_target(g_counts0[w], lvl, tgt);
    g_keep1[i] = (r < tgt) ? 1 : 0;
}

// Scalar outputs: keep, win0, win1, dl0, dl1, inner0, inner1 (as float)
__global__ void k_scalars(float* __restrict__ out, int N, int TILE) {
    int i = blockIdx.x * blockDim.x + threadIdx.x;
    if (i >= N) return;
    long Nl = N;
    int w0 = g_win0[i], w1 = g_win1[i], r0 = g_rank0[i];
    int lvl0, t0;
    level_target(g_counts0[w0], lvl0, t0);
    bool keep1 = g_keep1[i] != 0;
    int lvl1 = -1, r1o = -1;
    bool keepF = false;
    if (keep1) {
        int t = i / TILE;
        int r1 = g_rank1[i] + g_hist[(long)t * WNUM + w1];
        int tg;
        level_target(g_counts1[w1], lvl1, tg);
        r1o = r1;
        keepF = r1 < tg;
    }
    g_keepF[i] = keepF ? 1 : 0;
    out[128 * Nl + i] = keepF ? 1.0f : 0.0f;
    out[129 * Nl + i] = (float)w0;
    out[130 * Nl + i] = (float)w1;
    out[131 * Nl + i] = (float)lvl0;
    out[132 * Nl + i] = (float)lvl1;
    out[133 * Nl + i] = (float)r0;
    out[134 * Nl + i] = (float)r1o;
}

// Streaming outputs: feat_kept (masked copy), pe0, pe1 via the 3KB LUT in L1.
// One warp per token; each lane one float4.
template <bool VEC4>
__global__ void __launch_bounds__(256) k_vec(const float* __restrict__ feat,
                                             float* __restrict__ out, int N) {
    int warp = threadIdx.x >> 5;
    int lane = threadIdx.x & 31;
    int tok = blockIdx.x * (blockDim.x >> 5) + warp;
    if (tok >= N) return;

    unsigned cw = g_cw[tok];
    bool kf = g_keepF[tok] != 0;
    long Nl = N;
    int half = lane >> 4;  // 0: x-half (cols 0..63), 1: y-half (cols 64..127)
    int v0 = half ? ((cw >> 8) & 255) : (cw & 255);
    int v1 = half ? ((cw >> 24) & 255) : ((cw >> 16) & 255);

    if (VEC4) {
        int col = lane & 15;
        float4 f = ((const float4*)feat)[(long)tok * 32 + lane];
        if (!kf) { f.x = 0.f; f.y = 0.f; f.z = 0.f; f.w = 0.f; }
        ((float4*)out)[(long)tok * 32 + lane] = f;
        const float4* tab4 = (const float4*)g_tab;
        float4 p0 = tab4[v0 * 16 + col];
        float4 p1 = tab4[v1 * 16 + col];
        ((float4*)(out + 135 * Nl))[(long)tok * 32 + lane] = p0;
        ((float4*)(out + 263 * Nl))[(long)tok * 32 + lane] = p1;
    } else {
#pragma unroll
        for (int k = 0; k < 4; k++) {
            int c = lane * 4 + k;
            float f = feat[(long)tok * 128 + c];
            out[(long)tok * 128 + c] = kf ? f : 0.f;
            int cc = c & 63;
            out[135 * Nl + (long)tok * 128 + c] = g_tab[v0 * 64 + cc];
            out[263 * Nl + (long)tok * 128 + c] = g_tab[v1 * 64 + cc];
        }
    }
}

// ---------------- launch ----------------
extern "C" void kernel_launch(void* const* d_in, const int* in_sizes, int n_in,
                              void* d_out, int out_size) {
    const float* feat = (const float*)d_in[0];
    const int* coords = (const int*)d_in[1];
    float* out = (float*)d_out;
    int N = in_sizes[1] / 4;
    if (N > MAXN) N = MAXN;
    int TILE = (N + NT - 1) / NT;
    if (TILE < 32) TILE = 32;
    int T = (N + TILE - 1) / TILE;
    int nb = (N + 255) / 256;

    int tilepad = (TILE + 15) & ~15;
    int smem = WNUM * 4 + tilepad * 4 + tilepad;
    static bool attr_set = false;
    if (!attr_set) {
        cudaFuncSetAttribute(k_rankhist<0>, cudaFuncAttributeMaxDynamicSharedMemorySize, 64 * 1024);
        cudaFuncSetAttribute(k_rankhist<1>, cudaFuncAttributeMaxDynamicSharedMemorySize, 64 * 1024);
        attr_set = true;
    }

    k_table<<<1, 384>>>();
    k_prepare<<<nb, 256>>>(coords, N);

    // drop pass 0
    k_rankhist<0><<<T, 256, smem>>>(N, TILE);
    k_scan<0><<<(WNUM + 255) / 256, 256>>>(T);
    k_keep1<<<nb, 256>>>(N, TILE);

    // drop pass 1 (shifted windows, kept tokens only)
    k_rankhist<1><<<T, 256, smem>>>(N, TILE);
    k_scan<1><<<(WNUM + 255) / 256, 256>>>(T);

    k_scalars<<<nb, 256>>>(out, N, TILE);

    int vb = (N + 7) / 8;
    if ((N & 3) == 0) k_vec<true><<<vb, 256>>>(feat, out, N);
    else              k_vec<false><<<vb, 256>>>(feat, out, N);
}

// round 4
// speedup vs baseline: 4.4659x; 1.2010x over previous
#include <cuda_runtime.h>
#include <math.h>

// ---------------- problem constants ----------------
// SPARSE_SHAPE=(468,468,1), WINDOW=(12,12,1), BATCH=4
// _NX=_NY=40, _NZ=2, per_sample=3200, NUM_WINDOWS=12800
// window id = b*3200 + winx*80 + winy*2 + z  in [0, 12800)
#define WNUM 12800
#define MAXN 310016
#define NT 148          // tiles == SM count; one rank block per tile
#define MAXT 150

// ---------------- static scratch ----------------
__device__ int g_win0[MAXN];
__device__ int g_win1[MAXN];
__device__ int g_rank0[MAXN];   // pass0 rank (partial, finalized in k_rank1)
__device__ int g_rank1[MAXN];   // pass1 rank (partial; finalized in k_vec)
__device__ unsigned g_cw[MAXN]; // packed coords: x0|y0<<8|x1<<16|y1<<24
__device__ int g_h0[(long)MAXT * WNUM];  // tile-major hist / prefix, pass0
__device__ int g_h1[(long)MAXT * WNUM];  // pass1
__device__ int g_counts0[WNUM];
__device__ int g_counts1[WNUM];
__device__ float g_tab[12 * 64];         // sincos LUT

__device__ __forceinline__ void level_target(int n, int& lvl, int& tgt) {
    if (n < 16)      { lvl = 0; tgt = 16; }
    else if (n < 32) { lvl = 1; tgt = 32; }
    else if (n < 64) { lvl = 2; tgt = 64; }
    else             { lvl = 3; tgt = 144; }
}

// ---------------- pass 0: prepare + stable rank + per-tile histogram ----------------
// Block t handles tokens [t*TILE, t*TILE+len). Staging threads compute window
// ids from coords (fused "prepare"), warp 0 does the ordered match_any walk
// against shared counters, then the histogram is dumped coalesced.
__global__ void __launch_bounds__(256) k_rank0(const int* __restrict__ coords, int N, int TILE) {
    extern __shared__ int sh[];
    int* cnt = sh;                               // WNUM ints
    int tilepad = (TILE + 15) & ~15;
    int* swin = sh + WNUM;                       // tilepad ints
    int t = blockIdx.x, tid = threadIdx.x;
    int start = t * TILE;
    int len = min(TILE, N - start);
    if (len < 0) len = 0;

    // build the sincos LUT once (block 0); identical values if raced: benign
    if (t == 0) {
        for (int j = tid; j < 384; j += 256) {
            int v = j >> 5, fi = j & 31;
            // inv_freq = 10000^(fi/32); ln(10000)/32
            double inv = exp((double)fi * 0.28782313662425575);
            float arg = (float)(((double)(v - 6)) / inv);
            float s, c;
            sincosf(arg, &s, &c);
            g_tab[v * 64 + 2 * fi]     = s;
            g_tab[v * 64 + 2 * fi + 1] = c;
        }
    }

    for (int j = tid; j < WNUM; j += 256) cnt[j] = 0;
    for (int j = tid; j < len; j += 256) {
        int i = start + j;
        int4 c4 = ((const int4*)coords)[i];     // (b, z, y, x)
        int b = c4.x, z = c4.y, y = c4.z, x = c4.w;
        int cx0 = x + 12, cy0 = y + 12;         // do_shift=False (sz=0)
        int cx1 = x + 6,  cy1 = y + 6;          // do_shift=True  (sz=0)
        int w0 = b * 3200 + (cx0 / 12) * 80 + (cy0 / 12) * 2 + z;
        int w1 = b * 3200 + (cx1 / 12) * 80 + (cy1 / 12) * 2 + z;
        g_win0[i] = w0;
        g_win1[i] = w1;
        g_cw[i] = (unsigned)(cx0 % 12) | ((unsigned)(cy0 % 12) << 8) |
                  ((unsigned)(cx1 % 12) << 16) | ((unsigned)(cy1 % 12) << 24);
        swin[j] = w0;
    }
    __syncthreads();

    if (tid < 32) {
        int lane = tid;
        for (int base = 0; base < len; base += 32) {
            int j = base + lane;
            bool inb = j < len;
            int w = inb ? swin[j] : (WNUM + lane);
            unsigned peers = __match_any_sync(0xffffffffu, w);
            int leader = __ffs(peers) - 1;
            int r = __popc(peers & ((1u << lane) - 1u));
            int basec = 0;
            if (inb && lane == leader) {
                basec = cnt[w];
                cnt[w] = basec + __popc(peers);
            }
            basec = __shfl_sync(0xffffffffu, basec, leader);
            if (inb) g_rank0[start + j] = basec + r;
            __syncwarp();
        }
    }
    __syncthreads();

    int* hrow = g_h0 + (long)t * WNUM;
    for (int j = tid; j < WNUM; j += 256) hrow[j] = cnt[j];
}

// ---------------- pass 1: finalize rank0/keep + rank among kept in win1 ----------------
__global__ void __launch_bounds__(256) k_rank1(int N, int TILE) {
    extern __shared__ int sh[];
    int* cnt = sh;
    int tilepad = (TILE + 15) & ~15;
    int* swin = sh + WNUM;
    unsigned char* skeep = (unsigned char*)(swin + tilepad);
    int t = blockIdx.x, tid = threadIdx.x;
    int start = t * TILE;
    int len = min(TILE, N - start);
    if (len < 0) len = 0;
    const int* pref0 = g_h0 + (long)t * WNUM;

    for (int j = tid; j < WNUM; j += 256) cnt[j] = 0;
    for (int j = tid; j < len; j += 256) {
        int i = start + j;
        int w0 = g_win0[i];
        int r0 = g_rank0[i] + pref0[w0];   // finalize pass-0 rank
        g_rank0[i] = r0;
        int lvl, tgt;
        level_target(g_counts0[w0], lvl, tgt);
        bool keep = r0 < tgt;
        skeep[j] = keep ? 1 : 0;
        swin[j] = g_win1[i];
    }
    __syncthreads();

    if (tid < 32) {
        int lane = tid;
        for (int base = 0; base < len; base += 32) {
            int j = base + lane;
            bool inb = j < len;
            bool valid = inb && skeep[j];
            int w = valid ? swin[j] : (WNUM + lane);
            unsigned peers = __match_any_sync(0xffffffffu, w);
            int leader = __ffs(peers) - 1;
            int r = __popc(peers & ((1u << lane) - 1u));
            int basec = 0;
            if (valid && lane == leader) {
                basec = cnt[w];
                cnt[w] = basec + __popc(peers);
            }
            basec = __shfl_sync(0xffffffffu, basec, leader);
            if (inb) g_rank1[start + j] = valid ? (basec + r) : 0;
            __syncwarp();
        }
    }
    __syncthreads();

    int* hrow = g_h1 + (long)t * WNUM;
    for (int j = tid; j < WNUM; j += 256) hrow[j] = cnt[j];
}

// ---------------- parallel per-window exclusive scan over tiles ----------------
// 32 windows per block; coalesced stage -> 8-lane segmented scan -> coalesced store.
template <int PASS>
__global__ void __launch_bounds__(256) k_scan(int T) {
    __shared__ int s[NT * 33];
    int* hist = (PASS == 0) ? g_h0 : g_h1;
    int* counts = (PASS == 0) ? g_counts0 : g_counts1;
    int w0 = blockIdx.x * 32;
    int tid = threadIdx.x;
    for (int i = tid; i < T * 32; i += 256) {
        int t = i >> 5, w = i & 31;
        s[t * 33 + w] = hist[(long)t * WNUM + w0 + w];
    }
    __syncthreads();

    int w = tid >> 3, sub = tid & 7;
    int chunk = (T + 7) >> 3;
    int lo = sub * chunk, hi = min(lo + chunk, T);
    int partial = 0;
    for (int t = lo; t < hi; t++) partial += s[t * 33 + w];
    int inc = partial;
#pragma unroll
    for (int d = 1; d < 8; d <<= 1) {
        int v = __shfl_up_sync(0xffffffffu, inc, d, 8);
        if (sub >= d) inc += v;
    }
    int run = inc - partial;   // exclusive base for this segment
    for (int t = lo; t < hi; t++) {
        int v = s[t * 33 + w];
        s[t * 33 + w] = run;
        run += v;
    }
    if (sub == 7) counts[w0 + w] = inc;  // sub 7 holds the inclusive total
    __syncthreads();

    for (int i = tid; i < T * 32; i += 256) {
        int t = i >> 5, ww = i & 31;
        hist[(long)t * WNUM + w0 + ww] = s[t * 33 + ww];
    }
}

// ---------------- streaming outputs + fused scalars ----------------
// One warp per token. Lanes: float4 feat copy (masked), pe0/pe1 from 3KB LUT;
// lanes 0..6 additionally write keep/win0/win1/dl0/dl1/inner0/inner1.
template <bool VEC4>
__global__ void __launch_bounds__(256) k_vec(const float* __restrict__ feat,
                                             float* __restrict__ out, int N, int TILE) {
    int warp = threadIdx.x >> 5;
    int lane = threadIdx.x & 31;
    int tok = blockIdx.x * (blockDim.x >> 5) + warp;
    if (tok >= N) return;
    long Nl = N;

    // warp-uniform scalar computation (broadcast loads)
    int w0 = g_win0[tok], w1 = g_win1[tok];
    int r0 = g_rank0[tok];
    int lvl0, t0;
    level_target(g_counts0[w0], lvl0, t0);
    bool keep1 = r0 < t0;
    int dl1 = -1, r1o = -1;
    bool keepF = false;
    if (keep1) {
        int t = tok / TILE;
        int r1 = g_rank1[tok] + g_h1[(long)t * WNUM + w1];
        int lvl, tg;
        level_target(g_counts1[w1], lvl, tg);
        dl1 = lvl;
        r1o = r1;
        keepF = r1 < tg;
    }
    if (lane < 7) {
        float sv;
        switch (lane) {
            case 0: sv = keepF ? 1.0f : 0.0f; break;
            case 1: sv = (float)w0; break;
            case 2: sv = (float)w1; break;
            case 3: sv = (float)lvl0; break;
            case 4: sv = (float)dl1; break;
            case 5: sv = (float)r0; break;
            default: sv = (float)r1o; break;
        }
        out[(long)(128 + lane) * Nl + tok] = sv;
    }

    unsigned cw = g_cw[tok];
    int half = lane >> 4;  // 0: x-half (cols 0..63), 1: y-half (64..127)
    int v0 = half ? ((cw >> 8) & 255) : (cw & 255);
    int v1 = half ? ((cw >> 24) & 255) : ((cw >> 16) & 255);
    bool kf = keepF;

    if (VEC4) {
        int col = lane & 15;
        float4 f = ((const float4*)feat)[(long)tok * 32 + lane];
        if (!kf) { f.x = 0.f; f.y = 0.f; f.z = 0.f; f.w = 0.f; }
        ((float4*)out)[(long)tok * 32 + lane] = f;
        const float4* tab4 = (const float4*)g_tab;
        float4 p0 = tab4[v0 * 16 + col];
        float4 p1 = tab4[v1 * 16 + col];
        ((float4*)(out + 135 * Nl))[(long)tok * 32 + lane] = p0;
        ((float4*)(out + 263 * Nl))[(long)tok * 32 + lane] = p1;
    } else {
#pragma unroll
        for (int k = 0; k < 4; k++) {
            int c = lane * 4 + k;
            float f = feat[(long)tok * 128 + c];
            out[(long)tok * 128 + c] = kf ? f : 0.f;
            int cc = c & 63;
            out[135 * Nl + (long)tok * 128 + c] = g_tab[v0 * 64 + cc];
            out[263 * Nl + (long)tok * 128 + c] = g_tab[v1 * 64 + cc];
        }
    }
}

// ---------------- launch ----------------
extern "C" void kernel_launch(void* const* d_in, const int* in_sizes, int n_in,
                              void* d_out, int out_size) {
    const float* feat = (const float*)d_in[0];
    const int* coords = (const int*)d_in[1];
    float* out = (float*)d_out;
    int N = in_sizes[1] / 4;
    if (N > MAXN) N = MAXN;
    int TILE = (N + NT - 1) / NT;
    if (TILE < 32) TILE = 32;
    int T = (N + TILE - 1) / TILE;

    int tilepad = (TILE + 15) & ~15;
    int smem = WNUM * 4 + tilepad * 4 + tilepad;
    cudaFuncSetAttribute(k_rank0, cudaFuncAttributeMaxDynamicSharedMemorySize, 64 * 1024);
    cudaFuncSetAttribute(k_rank1, cudaFuncAttributeMaxDynamicSharedMemorySize, 64 * 1024);

    k_rank0<<<T, 256, smem>>>(coords, N, TILE);
    k_scan<0><<<WNUM / 32, 256>>>(T);
    k_rank1<<<T, 256, smem>>>(N, TILE);
    k_scan<1><<<WNUM / 32, 256>>>(T);

    int vb = (N + 7) / 8;
    if ((N & 3) == 0) k_vec<true><<<vb, 256>>>(feat, out, N, TILE);
    else              k_vec<false><<<vb, 256>>>(feat, out, N, TILE);
}

// round 5
// speedup vs baseline: 5.8726x; 1.3150x over previous
#include <cuda_runtime.h>
#include <math.h>

// ---------------- problem constants ----------------
// SPARSE_SHAPE=(468,468,1), WINDOW=(12,12,1), BATCH=4
// _NX=_NY=40, _NZ=2, per_sample=3200, NUM_WINDOWS=12800
// full id = b*3200 + wx*80 + wy*2 + z ; dataset has z==0 for all tokens,
// so id = 2*(b*1600 + wx*40 + wy): compressed counting id = id>>1 in [0,6400)
#define WC 6400
#define MAXN 310016
#define NTIL 296        // 2 rank blocks per SM
#define MAXT 300

// ---------------- static scratch ----------------
__device__ int g_win0[MAXN];
__device__ int g_win1[MAXN];
__device__ int g_rank0[MAXN];    // pass0 rank (partial, finalized in k_rank1)
__device__ int g_rank1[MAXN];    // pass1 rank (partial; finalized in k_vec)
__device__ unsigned g_cw[MAXN];  // packed coords: x0|y0<<8|x1<<16|y1<<24
__device__ unsigned short g_h0[(long)MAXT * WC];  // tile-major hist/prefix
__device__ unsigned short g_h1[(long)MAXT * WC];
__device__ int g_counts0[WC];
__device__ int g_counts1[WC];
__device__ float g_tab[12 * 64]; // sincos LUT

__device__ __forceinline__ void level_target(int n, int& lvl, int& tgt) {
    if (n < 16)      { lvl = 0; tgt = 16; }
    else if (n < 32) { lvl = 1; tgt = 32; }
    else if (n < 64) { lvl = 2; tgt = 64; }
    else             { lvl = 3; tgt = 144; }
}

// ---------------- pass 0: prepare + stable rank + per-tile histogram ----------------
__global__ void __launch_bounds__(256) k_rank0(const int* __restrict__ coords, int N, int TILE) {
    extern __shared__ int sh[];
    int* cnt = sh;                          // WC ints
    int tilepad = (TILE + 15) & ~15;
    int* swin = sh + WC;                    // tilepad ints (compressed win0)
    int t = blockIdx.x, tid = threadIdx.x;
    int start = t * TILE;
    int len = min(TILE, N - start);
    if (len < 0) len = 0;

    // sincos LUT, built by block 0 (cheap fp32 path)
    if (t == 0) {
        for (int j = tid; j < 384; j += 256) {
            int v = j >> 5, fi = j & 31;
            // inv_freq = 10000^(fi/32) = 2^(fi*log2(1e4)/32)
            float inv = exp2f((float)fi * 0.41524101186092029f);
            float arg = (float)(v - 6) / inv;
            float s, c;
            sincosf(arg, &s, &c);
            g_tab[v * 64 + 2 * fi]     = s;
            g_tab[v * 64 + 2 * fi + 1] = c;
        }
    }

    for (int j = tid; j < WC; j += 256) cnt[j] = 0;
    for (int j = tid; j < len; j += 256) {
        int i = start + j;
        int4 c4 = ((const int4*)coords)[i];     // (b, z, y, x)
        int b = c4.x, z = c4.y, y = c4.z, x = c4.w;
        int cx0 = x + 12, cy0 = y + 12;         // do_shift=False (sz=0)
        int cx1 = x + 6,  cy1 = y + 6;          // do_shift=True  (sz=0)
        int w0 = b * 3200 + (cx0 / 12) * 80 + (cy0 / 12) * 2 + z;
        int w1 = b * 3200 + (cx1 / 12) * 80 + (cy1 / 12) * 2 + z;
        g_win0[i] = w0;
        g_win1[i] = w1;
        g_cw[i] = (unsigned)(cx0 % 12) | ((unsigned)(cy0 % 12) << 8) |
                  ((unsigned)(cx1 % 12) << 16) | ((unsigned)(cy1 % 12) << 24);
        swin[j] = w0 >> 1;                      // compressed (z==0 dataset)
    }
    __syncthreads();

    if (tid < 32) {
        int lane = tid;
        for (int base = 0; base < len; base += 32) {
            int j = base + lane;
            bool inb = j < len;
            int w = inb ? swin[j] : (WC + lane);
            unsigned peers = __match_any_sync(0xffffffffu, w);
            int leader = __ffs(peers) - 1;
            int r = __popc(peers & ((1u << lane) - 1u));
            int basec = 0;
            if (inb && lane == leader) {
                basec = cnt[w];
                cnt[w] = basec + __popc(peers);
            }
            basec = __shfl_sync(0xffffffffu, basec, leader);
            if (inb) g_rank0[start + j] = basec + r;
            __syncwarp();
        }
    }
    __syncthreads();

    unsigned short* hrow = g_h0 + (long)t * WC;
    for (int j = tid; j < WC; j += 256) hrow[j] = (unsigned short)cnt[j];
}

// ---------------- pass 1: finalize rank0/keep + rank among kept in win1 ----------------
__global__ void __launch_bounds__(256) k_rank1(int N, int TILE) {
    extern __shared__ int sh[];
    int* cnt = sh;
    int tilepad = (TILE + 15) & ~15;
    int* swin = sh + WC;
    unsigned char* skeep = (unsigned char*)(swin + tilepad);
    int t = blockIdx.x, tid = threadIdx.x;
    int start = t * TILE;
    int len = min(TILE, N - start);
    if (len < 0) len = 0;
    const unsigned short* pref0 = g_h0 + (long)t * WC;

    for (int j = tid; j < WC; j += 256) cnt[j] = 0;
    for (int j = tid; j < len; j += 256) {
        int i = start + j;
        int c0 = g_win0[i] >> 1;
        int r0 = g_rank0[i] + (int)pref0[c0];   // finalize pass-0 rank
        g_rank0[i] = r0;
        int lvl, tgt;
        level_target(g_counts0[c0], lvl, tgt);
        skeep[j] = (r0 < tgt) ? 1 : 0;
        swin[j] = g_win1[i] >> 1;
    }
    __syncthreads();

    if (tid < 32) {
        int lane = tid;
        for (int base = 0; base < len; base += 32) {
            int j = base + lane;
            bool inb = j < len;
            bool valid = inb && skeep[j];
            int w = valid ? swin[j] : (WC + lane);
            unsigned peers = __match_any_sync(0xffffffffu, w);
            int leader = __ffs(peers) - 1;
            int r = __popc(peers & ((1u << lane) - 1u));
            int basec = 0;
            if (valid && lane == leader) {
                basec = cnt[w];
                cnt[w] = basec + __popc(peers);
            }
            basec = __shfl_sync(0xffffffffu, basec, leader);
            if (inb) g_rank1[start + j] = valid ? (basec + r) : 0;
            __syncwarp();
        }
    }
    __syncthreads();

    unsigned short* hrow = g_h1 + (long)t * WC;
    for (int j = tid; j < WC; j += 256) hrow[j] = (unsigned short)cnt[j];
}

// ---------------- parallel per-window exclusive scan over tiles ----------------
// 32 windows per block (200 blocks); stage coalesced, 8-lane segmented scan.
template <int PASS>
__global__ void __launch_bounds__(256) k_scan(int T) {
    __shared__ int s[MAXT * 33];
    unsigned short* hist = (PASS == 0) ? g_h0 : g_h1;
    int* counts = (PASS == 0) ? g_counts0 : g_counts1;
    int w0 = blockIdx.x * 32;
    int tid = threadIdx.x;
    for (int i = tid; i < T * 32; i += 256) {
        int t = i >> 5, w = i & 31;
        s[t * 33 + w] = hist[(long)t * WC + w0 + w];
    }
    __syncthreads();

    int w = tid >> 3, sub = tid & 7;
    int chunk = (T + 7) >> 3;
    int lo = sub * chunk, hi = min(lo + chunk, T);
    int partial = 0;
    for (int t = lo; t < hi; t++) partial += s[t * 33 + w];
    int inc = partial;
#pragma unroll
    for (int d = 1; d < 8; d <<= 1) {
        int v = __shfl_up_sync(0xffffffffu, inc, d, 8);
        if (sub >= d) inc += v;
    }
    int run = inc - partial;   // exclusive base of this segment
    for (int t = lo; t < hi; t++) {
        int v = s[t * 33 + w];
        s[t * 33 + w] = run;
        run += v;
    }
    if (sub == 7) counts[w0 + w] = inc;  // inclusive total
    __syncthreads();

    for (int i = tid; i < T * 32; i += 256) {
        int t = i >> 5, ww = i & 31;
        hist[(long)t * WC + w0 + ww] = (unsigned short)s[t * 33 + ww];
    }
}

// ---------------- streaming outputs + fused scalars ----------------
template <bool VEC4>
__global__ void __launch_bounds__(256) k_vec(const float* __restrict__ feat,
                                             float* __restrict__ out, int N, int TILE) {
    int warp = threadIdx.x >> 5;
    int lane = threadIdx.x & 31;
    int tok = blockIdx.x * (blockDim.x >> 5) + warp;
    if (tok >= N) return;
    long Nl = N;

    int w0 = g_win0[tok], w1 = g_win1[tok];
    int c0 = w0 >> 1, c1 = w1 >> 1;
    int r0 = g_rank0[tok];
    int lvl0, t0;
    level_target(g_counts0[c0], lvl0, t0);
    bool keep1 = r0 < t0;
    int dl1 = -1, r1o = -1;
    bool keepF = false;
    if (keep1) {
        int t = tok / TILE;
        int r1 = g_rank1[tok] + (int)g_h1[(long)t * WC + c1];
        int lvl, tg;
        level_target(g_counts1[c1], lvl, tg);
        dl1 = lvl;
        r1o = r1;
        keepF = r1 < tg;
    }
    if (lane < 7) {
        float sv;
        switch (lane) {
            case 0: sv = keepF ? 1.0f : 0.0f; break;
            case 1: sv = (float)w0; break;
            case 2: sv = (float)w1; break;
            case 3: sv = (float)lvl0; break;
            case 4: sv = (float)dl1; break;
            case 5: sv = (float)r0; break;
            default: sv = (float)r1o; break;
        }
        __stcs(&out[(long)(128 + lane) * Nl + tok], sv);
    }

    unsigned cw = g_cw[tok];
    int half = lane >> 4;  // 0: x-half (cols 0..63), 1: y-half (64..127)
    int v0 = half ? ((cw >> 8) & 255) : (cw & 255);
    int v1 = half ? ((cw >> 24) & 255) : ((cw >> 16) & 255);
    bool kf = keepF;

    if (VEC4) {
        int col = lane & 15;
        float4 f = __ldcs(&((const float4*)feat)[(long)tok * 32 + lane]);
        if (!kf) { f.x = 0.f; f.y = 0.f; f.z = 0.f; f.w = 0.f; }
        __stcs(&((float4*)out)[(long)tok * 32 + lane], f);
        const float4* tab4 = (const float4*)g_tab;
        float4 p0 = tab4[v0 * 16 + col];
        float4 p1 = tab4[v1 * 16 + col];
        __stcs(&((float4*)(out + 135 * Nl))[(long)tok * 32 + lane], p0);
        __stcs(&((float4*)(out + 263 * Nl))[(long)tok * 32 + lane], p1);
    } else {
#pragma unroll
        for (int k = 0; k < 4; k++) {
            int c = lane * 4 + k;
            float f = feat[(long)tok * 128 + c];
            out[(long)tok * 128 + c] = kf ? f : 0.f;
            int cc = c & 63;
            out[135 * Nl + (long)tok * 128 + c] = g_tab[v0 * 64 + cc];
            out[263 * Nl + (long)tok * 128 + c] = g_tab[v1 * 64 + cc];
        }
    }
}

// ---------------- launch ----------------
extern "C" void kernel_launch(void* const* d_in, const int* in_sizes, int n_in,
                              void* d_out, int out_size) {
    const float* feat = (const float*)d_in[0];
    const int* coords = (const int*)d_in[1];
    float* out = (float*)d_out;
    int N = in_sizes[1] / 4;
    if (N > MAXN) N = MAXN;
    int TILE = (N + NTIL - 1) / NTIL;
    if (TILE < 32) TILE = 32;
    int T = (N + TILE - 1) / TILE;

    int tilepad = (TILE + 15) & ~15;
    int smem = WC * 4 + tilepad * 4 + tilepad;   // < 48KB, no attr needed

    k_rank0<<<T, 256, smem>>>(coords, N, TILE);
    k_scan<0><<<WC / 32, 256>>>(T);
    k_rank1<<<T, 256, smem>>>(N, TILE);
    k_scan<1><<<WC / 32, 256>>>(T);

    int vb = (N + 7) / 8;
    if ((N & 3) == 0) k_vec<true><<<vb, 256>>>(feat, out, N, TILE);
    else              k_vec<false><<<vb, 256>>>(feat, out, N, TILE);
}

// round 7
// speedup vs baseline: 6.0692x; 1.0335x over previous
#include <cuda_runtime.h>
#include <math.h>

// ---------------- problem constants ----------------
// SPARSE_SHAPE=(468,468,1), WINDOW=(12,12,1), BATCH=4
// full id = b*3200 + wx*80 + wy*2 + z ; dataset has z==0 always,
// so compressed counting id = id>>1 = b*1600 + wx*40 + wy in [0, 6400)
#define WC 6400
#define MAXN 310016
#define NTIL 592        // 4 rank blocks per SM
#define MAXT 600

// ---------------- static scratch ----------------
__device__ int g_win0[MAXN];
__device__ int g_win1[MAXN];
__device__ int g_rank0[MAXN];    // pass0 rank (partial, finalized in k_rank1)
__device__ int g_rank1[MAXN];    // pass1 rank (partial; finalized in k_vec)
__device__ unsigned g_cw[MAXN];  // packed coords: x0|y0<<8|x1<<16|y1<<24
__device__ unsigned short g_h0[(long)MAXT * WC];  // tile-major hist/prefix
__device__ unsigned short g_h1[(long)MAXT * WC];
__device__ int g_counts0[WC];
__device__ int g_counts1[WC];
__device__ float g_tab[12 * 64]; // sincos LUT

__device__ __forceinline__ void level_target(int n, int& lvl, int& tgt) {
    if (n < 16)      { lvl = 0; tgt = 16; }
    else if (n < 32) { lvl = 1; tgt = 32; }
    else if (n < 64) { lvl = 2; tgt = 64; }
    else             { lvl = 3; tgt = 144; }
}

// ---------------- pass 0: prepare + stable rank + per-tile histogram ----------------
__global__ void __launch_bounds__(256) k_rank0(const int* __restrict__ coords, int N, int TILE) {
    extern __shared__ unsigned short sh16[];
    unsigned short* cnt = sh16;                  // WC u16
    int tilepad = (TILE + 15) & ~15;
    unsigned short* swin = sh16 + WC;            // tilepad u16 (compressed win0)
    int t = blockIdx.x, tid = threadIdx.x;
    int start = t * TILE;
    int len = min(TILE, N - start);
    if (len < 0) len = 0;

    // sincos LUT, built by block 0 (fp32)
    if (t == 0) {
        for (int j = tid; j < 384; j += 256) {
            int v = j >> 5, fi = j & 31;
            // inv_freq = 10000^(fi/32) = 2^(fi*log2(1e4)/32)
            float inv = exp2f((float)fi * 0.41524101186092029f);
            float arg = (float)(v - 6) / inv;
            float s, c;
            sincosf(arg, &s, &c);
            g_tab[v * 64 + 2 * fi]     = s;
            g_tab[v * 64 + 2 * fi + 1] = c;
        }
    }

    for (int j = tid; j < WC; j += 256) cnt[j] = 0;
    for (int j = tid; j < len; j += 256) {
        int i = start + j;
        int4 c4 = ((const int4*)coords)[i];     // (b, z, y, x)
        int b = c4.x, z = c4.y, y = c4.z, x = c4.w;
        int cx0 = x + 12, cy0 = y + 12;         // do_shift=False (sz=0)
        int cx1 = x + 6,  cy1 = y + 6;          // do_shift=True  (sz=0)
        int w0 = b * 3200 + (cx0 / 12) * 80 + (cy0 / 12) * 2 + z;
        int w1 = b * 3200 + (cx1 / 12) * 80 + (cy1 / 12) * 2 + z;
        g_win0[i] = w0;
        g_win1[i] = w1;
        g_cw[i] = (unsigned)(cx0 % 12) | ((unsigned)(cy0 % 12) << 8) |
                  ((unsigned)(cx1 % 12) << 16) | ((unsigned)(cy1 % 12) << 24);
        swin[j] = (unsigned short)(w0 >> 1);    // compressed (z==0)
    }
    __syncthreads();

    if (tid < 32) {
        int lane = tid;
        for (int base = 0; base < len; base += 32) {
            int j = base + lane;
            bool inb = j < len;
            int w = inb ? (int)swin[j] : (WC + lane);
            unsigned peers = __match_any_sync(0xffffffffu, w);
            int leader = __ffs(peers) - 1;
            int r = __popc(peers & ((1u << lane) - 1u));
            int basec = 0;
            if (inb && lane == leader) {
                basec = (int)cnt[w];
                cnt[w] = (unsigned short)(basec + __popc(peers));
            }
            basec = __shfl_sync(0xffffffffu, basec, leader);
            if (inb) g_rank0[start + j] = basec + r;
            __syncwarp();
        }
    }
    __syncthreads();

    unsigned short* hrow = g_h0 + (long)t * WC;
    for (int j = tid; j < WC; j += 256) hrow[j] = cnt[j];
}

// ---------------- pass 1: finalize rank0/keep + rank among kept in win1 ----------------
__global__ void __launch_bounds__(256) k_rank1(int N, int TILE) {
    extern __shared__ unsigned short sh16[];
    unsigned short* cnt = sh16;
    int tilepad = (TILE + 15) & ~15;
    unsigned short* swin = sh16 + WC;
    unsigned char* skeep = (unsigned char*)(swin + tilepad);
    int t = blockIdx.x, tid = threadIdx.x;
    int start = t * TILE;
    int len = min(TILE, N - start);
    if (len < 0) len = 0;
    const unsigned short* pref0 = g_h0 + (long)t * WC;

    for (int j = tid; j < WC; j += 256) cnt[j] = 0;
    for (int j = tid; j < len; j += 256) {
        int i = start + j;
        int c0 = g_win0[i] >> 1;
        int r0 = g_rank0[i] + (int)pref0[c0];   // finalize pass-0 rank
        g_rank0[i] = r0;
        int lvl, tgt;
        level_target(g_counts0[c0], lvl, tgt);
        skeep[j] = (r0 < tgt) ? 1 : 0;
        swin[j] = (unsigned short)(g_win1[i] >> 1);
    }
    __syncthreads();

    if (tid < 32) {
        int lane = tid;
        for (int base = 0; base < len; base += 32) {
            int j = base + lane;
            bool inb = j < len;
            bool valid = inb && skeep[j];
            int w = valid ? (int)swin[j] : (WC + lane);
            unsigned peers = __match_any_sync(0xffffffffu, w);
            int leader = __ffs(peers) - 1;
            int r = __popc(peers & ((1u << lane) - 1u));
            int basec = 0;
            if (valid && lane == leader) {
                basec = (int)cnt[w];
                cnt[w] = (unsigned short)(basec + __popc(peers));
            }
            basec = __shfl_sync(0xffffffffu, basec, leader);
            if (inb) g_rank1[start + j] = valid ? (basec + r) : 0;
            __syncwarp();
        }
    }
    __syncthreads();

    unsigned short* hrow = g_h1 + (long)t * WC;
    for (int j = tid; j < WC; j += 256) hrow[j] = cnt[j];
}

// ---------------- parallel per-window exclusive scan over tiles ----------------
// 8 windows per block (800 blocks); 32-lane segmented scan per window.
template <int PASS>
__global__ void __launch_bounds__(256) k_scan(int T) {
    __shared__ int s[MAXT * 9];
    unsigned short* hist = (PASS == 0) ? g_h0 : g_h1;
    int* counts = (PASS == 0) ? g_counts0 : g_counts1;
    int w0 = blockIdx.x * 8;
    int tid = threadIdx.x;
    for (int i = tid; i < T * 8; i += 256) {
        int t = i >> 3, w = i & 7;
        s[t * 9 + w] = (int)hist[(long)t * WC + w0 + w];
    }
    __syncthreads();

    int w = tid >> 5, sub = tid & 31;
    int chunk = (T + 31) >> 5;
    int lo = sub * chunk, hi = min(lo + chunk, T);
    int partial = 0;
    for (int t = lo; t < hi; t++) partial += s[t * 9 + w];
    int inc = partial;
#pragma unroll
    for (int d = 1; d < 32; d <<= 1) {
        int v = __shfl_up_sync(0xffffffffu, inc, d);
        if (sub >= d) inc += v;
    }
    int run = inc - partial;   // exclusive base of this segment
    for (int t = lo; t < hi; t++) {
        int v = s[t * 9 + w];
        s[t * 9 + w] = run;
        run += v;
    }
    if (sub == 31) counts[w0 + w] = inc;  // inclusive total
    __syncthreads();

    for (int i = tid; i < T * 8; i += 256) {
        int t = i >> 3, ww = i & 7;
        hist[(long)t * WC + w0 + ww] = (unsigned short)s[t * 9 + ww];
    }
}

// ---------------- streaming outputs + fused scalars ----------------
template <bool VEC4>
__global__ void __launch_bounds__(256) k_vec(const float* __restrict__ feat,
                                             float* __restrict__ out, int N, int TILE) {
    int warp = threadIdx.x >> 5;
    int lane = threadIdx.x & 31;
    int tok = blockIdx.x * (blockDim.x >> 5) + warp;
    if (tok >= N) return;
    long Nl = N;

    int w0 = g_win0[tok], w1 = g_win1[tok];
    int c0 = w0 >> 1, c1 = w1 >> 1;
    int r0 = g_rank0[tok];
    int lvl0, t0;
    level_target(g_counts0[c0], lvl0, t0);
    bool keep1 = r0 < t0;
    int dl1 = -1, r1o = -1;
    bool keepF = false;
    if (keep1) {
        int t = tok / TILE;
        int r1 = g_rank1[tok] + (int)g_h1[(long)t * WC + c1];
        int lvl, tg;
        level_target(g_counts1[c1], lvl, tg);
        dl1 = lvl;
        r1o = r1;
        keepF = r1 < tg;
    }
    if (lane < 7) {
        float sv;
        switch (lane) {
            case 0: sv = keepF ? 1.0f : 0.0f; break;
            case 1: sv = (float)w0; break;
            case 2: sv = (float)w1; break;
            case 3: sv = (float)lvl0; break;
            case 4: sv = (float)dl1; break;
            case 5: sv = (float)r0; break;
            default: sv = (float)r1o; break;
        }
        __stcs(&out[(long)(128 + lane) * Nl + tok], sv);
    }

    unsigned cw = g_cw[tok];
    int half = lane >> 4;  // 0: x-half (cols 0..63), 1: y-half (64..127)
    int v0 = half ? ((cw >> 8) & 255) : (cw & 255);
    int v1 = half ? ((cw >> 24) & 255) : ((cw >> 16) & 255);
    bool kf = keepF;

    if (VEC4) {
        int col = lane & 15;
        float4 f = __ldcs(&((const float4*)feat)[(long)tok * 32 + lane]);
        if (!kf) { f.x = 0.f; f.y = 0.f; f.z = 0.f; f.w = 0.f; }
        __stcs(&((float4*)out)[(long)tok * 32 + lane], f);
        const float4* tab4 = (const float4*)g_tab;
        float4 p0 = tab4[v0 * 16 + col];
        float4 p1 = tab4[v1 * 16 + col];
        __stcs(&((float4*)(out + 135 * Nl))[(long)tok * 32 + lane], p0);
        __stcs(&((float4*)(out + 263 * Nl))[(long)tok * 32 + lane], p1);
    } else {
#pragma unroll
        for (int k = 0; k < 4; k++) {
            int c = lane * 4 + k;
            float f = feat[(long)tok * 128 + c];
            out[(long)tok * 128 + c] = kf ? f : 0.f;
            int cc = c & 63;
            out[135 * Nl + (long)tok * 128 + c] = g_tab[v0 * 64 + cc];
            out[263 * Nl + (long)tok * 128 + c] = g_tab[v1 * 64 + cc];
        }
    }
}

// ---------------- launch ----------------
extern "C" void kernel_launch(void* const* d_in, const int* in_sizes, int n_in,
                              void* d_out, int out_size) {
    const float* feat = (const float*)d_in[0];
    const int* coords = (const int*)d_in[1];
    float* out = (float*)d_out;
    int N = in_sizes[1] / 4;
    if (N > MAXN) N = MAXN;
    int TILE = (N + NTIL - 1) / NTIL;
    if (TILE < 32) TILE = 32;
    int T = (N + TILE - 1) / TILE;

    int tilepad = (TILE + 15) & ~15;
    int smem = WC * 2 + tilepad * 2 + tilepad;   // ~14.4KB

    k_rank0<<<T, 256, smem>>>(coords, N, TILE);
    k_scan<0><<<WC / 8, 256>>>(T);
    k_rank1<<<T, 256, smem>>>(N, TILE);
    k_scan<1><<<WC / 8, 256>>>(T);

    int vb = (N + 7) / 8;
    if ((N & 3) == 0) k_vec<true><<<vb, 256>>>(feat, out, N, TILE);
    else              k_vec<false><<<vb, 256>>>(feat, out, N, TILE);
}

// round 9
// speedup vs baseline: 6.2476x; 1.0294x over previous
#include <cuda_runtime.h>
#include <math.h>

// ---------------- problem constants ----------------
// SPARSE_SHAPE=(468,468,1), WINDOW=(12,12,1), BATCH=4
// full id = b*3200 + wx*80 + wy*2 + z ; dataset has z==0 always,
// so compressed counting id = id>>1 = b*1600 + wx*40 + wy in [0, 6400)
#define WC 6400
#define MAXN 310016
#define NTIL 592        // 4 rank blocks per SM
#define MAXT 600

// ---------------- static scratch ----------------
__device__ int g_win0[MAXN];
__device__ int g_win1[MAXN];
__device__ int g_rank0[MAXN];    // pass0 rank (partial, finalized in k_rank1)
__device__ int g_rank1[MAXN];    // pass1 rank (partial; finalized in k_vec)
__device__ unsigned g_cw[MAXN];  // packed coords: x0|y0<<8|x1<<16|y1<<24
__device__ unsigned short g_h0[(long)MAXT * WC];  // tile-major hist/prefix
__device__ unsigned short g_h1[(long)MAXT * WC];
__device__ int g_counts0[WC];
__device__ int g_counts1[WC];
__device__ float g_tab[12 * 64]; // sincos LUT

__device__ __forceinline__ void level_target(int n, int& lvl, int& tgt) {
    if (n < 16)      { lvl = 0; tgt = 16; }
    else if (n < 32) { lvl = 1; tgt = 32; }
    else if (n < 64) { lvl = 2; tgt = 64; }
    else             { lvl = 3; tgt = 144; }
}

// ---------------- pass 0: prepare + stable rank + per-tile histogram ----------------
__global__ void __launch_bounds__(256) k_rank0(const int* __restrict__ coords, int N, int TILE) {
    extern __shared__ unsigned short sh16[];
    unsigned short* cnt = sh16;                  // WC u16
    int tilepad = (TILE + 15) & ~15;
    unsigned short* swin = sh16 + WC;            // tilepad u16 (compressed win0)
    int t = blockIdx.x, tid = threadIdx.x;
    int start = t * TILE;
    int len = min(TILE, N - start);
    if (len < 0) len = 0;

    // sincos LUT, built by block 0 (fp32)
    if (t == 0) {
        for (int j = tid; j < 384; j += 256) {
            int v = j >> 5, fi = j & 31;
            // inv_freq = 10000^(fi/32) = 2^(fi*log2(1e4)/32)
            float inv = exp2f((float)fi * 0.41524101186092029f);
            float arg = (float)(v - 6) / inv;
            float s, c;
            sincosf(arg, &s, &c);
            g_tab[v * 64 + 2 * fi]     = s;
            g_tab[v * 64 + 2 * fi + 1] = c;
        }
    }

    for (int j = tid; j < WC; j += 256) cnt[j] = 0;
    for (int j = tid; j < len; j += 256) {
        int i = start + j;
        int4 c4 = ((const int4*)coords)[i];     // (b, z, y, x)
        int b = c4.x, z = c4.y, y = c4.z, x = c4.w;
        int cx0 = x + 12, cy0 = y + 12;         // do_shift=False (sz=0)
        int cx1 = x + 6,  cy1 = y + 6;          // do_shift=True  (sz=0)
        int w0 = b * 3200 + (cx0 / 12) * 80 + (cy0 / 12) * 2 + z;
        int w1 = b * 3200 + (cx1 / 12) * 80 + (cy1 / 12) * 2 + z;
        g_win0[i] = w0;
        g_win1[i] = w1;
        g_cw[i] = (unsigned)(cx0 % 12) | ((unsigned)(cy0 % 12) << 8) |
                  ((unsigned)(cx1 % 12) << 16) | ((unsigned)(cy1 % 12) << 24);
        swin[j] = (unsigned short)(w0 >> 1);    // compressed (z==0)
    }
    __syncthreads();

    if (tid < 32) {
        int lane = tid;
        for (int base = 0; base < len; base += 32) {
            int j = base + lane;
            bool inb = j < len;
            int w = inb ? (int)swin[j] : (WC + lane);
            unsigned peers = __match_any_sync(0xffffffffu, w);
            int leader = __ffs(peers) - 1;
            int r = __popc(peers & ((1u << lane) - 1u));
            int basec = 0;
            if (inb && lane == leader) {
                basec = (int)cnt[w];
                cnt[w] = (unsigned short)(basec + __popc(peers));
            }
            basec = __shfl_sync(0xffffffffu, basec, leader);
            if (inb) g_rank0[start + j] = basec + r;
            __syncwarp();
        }
    }
    __syncthreads();

    unsigned short* hrow = g_h0 + (long)t * WC;
    for (int j = tid; j < WC; j += 256) hrow[j] = cnt[j];
}

// ---------------- pass 1: finalize rank0/keep + rank among kept in win1 ----------------
__global__ void __launch_bounds__(256) k_rank1(int N, int TILE) {
    extern __shared__ unsigned short sh16[];
    unsigned short* cnt = sh16;
    int tilepad = (TILE + 15) & ~15;
    unsigned short* swin = sh16 + WC;
    unsigned char* skeep = (unsigned char*)(swin + tilepad);
    int t = blockIdx.x, tid = threadIdx.x;
    int start = t * TILE;
    int len = min(TILE, N - start);
    if (len < 0) len = 0;
    const unsigned short* pref0 = g_h0 + (long)t * WC;

    for (int j = tid; j < WC; j += 256) cnt[j] = 0;
    for (int j = tid; j < len; j += 256) {
        int i = start + j;
        int c0 = g_win0[i] >> 1;
        int r0 = g_rank0[i] + (int)pref0[c0];   // finalize pass-0 rank
        g_rank0[i] = r0;
        int lvl, tgt;
        level_target(g_counts0[c0], lvl, tgt);
        skeep[j] = (r0 < tgt) ? 1 : 0;
        swin[j] = (unsigned short)(g_win1[i] >> 1);
    }
    __syncthreads();

    if (tid < 32) {
        int lane = tid;
        for (int base = 0; base < len; base += 32) {
            int j = base + lane;
            bool inb = j < len;
            bool valid = inb && skeep[j];
            int w = valid ? (int)swin[j] : (WC + lane);
            unsigned peers = __match_any_sync(0xffffffffu, w);
            int leader = __ffs(peers) - 1;
            int r = __popc(peers & ((1u << lane) - 1u));
            int basec = 0;
            if (valid && lane == leader) {
                basec = (int)cnt[w];
                cnt[w] = (unsigned short)(basec + __popc(peers));
            }
            basec = __shfl_sync(0xffffffffu, basec, leader);
            if (inb) g_rank1[start + j] = valid ? (basec + r) : 0;
            __syncwarp();
        }
    }
    __syncthreads();

    unsigned short* hrow = g_h1 + (long)t * WC;
    for (int j = tid; j < WC; j += 256) hrow[j] = cnt[j];
}

// ---------------- parallel per-window exclusive scan over tiles ----------------
// 16 windows per block (400 blocks); every tile-row access = one full 32B
// sector; ushort4 quad loads/stores; 16-lane segmented shfl scan per window.
template <int PASS>
__global__ void __launch_bounds__(256) k_scan(int T) {
    __shared__ unsigned short s[MAXT * 17];
    unsigned short* hist = (PASS == 0) ? g_h0 : g_h1;
    int* counts = (PASS == 0) ? g_counts0 : g_counts1;
    int w0 = blockIdx.x * 16;
    int tid = threadIdx.x;

    int nq = T * 4;                         // 4 ushort4 quads per tile-row
    for (int i = tid; i < nq; i += 256) {
        int t = i >> 2, q = (i & 3) * 4;
        ushort4 v = *(const ushort4*)&hist[(long)t * WC + w0 + q];
        s[t * 17 + q + 0] = v.x;
        s[t * 17 + q + 1] = v.y;
        s[t * 17 + q + 2] = v.z;
        s[t * 17 + q + 3] = v.w;
    }
    __syncthreads();

    int w = tid >> 4, sub = tid & 15;       // 16 windows x 16 lanes
    int chunk = (T + 15) >> 4;
    int lo = sub * chunk, hi = min(lo + chunk, T);
    int partial = 0;
    for (int t = lo; t < hi; t++) partial += (int)s[t * 17 + w];
    int inc = partial;
#pragma unroll
    for (int d = 1; d < 16; d <<= 1) {
        int v = __shfl_up_sync(0xffffffffu, inc, d, 16);
        if (sub >= d) inc += v;
    }
    int run = inc - partial;                // exclusive base of this segment
    for (int t = lo; t < hi; t++) {
        int v = (int)s[t * 17 + w];
        s[t * 17 + w] = (unsigned short)run;
        run += v;
    }
    if (sub == 15) counts[w0 + w] = inc;    // inclusive total
    __syncthreads();

    for (int i = tid; i < nq; i += 256) {
        int t = i >> 2, q = (i & 3) * 4;
        ushort4 v;
        v.x = s[t * 17 + q + 0];
        v.y = s[t * 17 + q + 1];
        v.z = s[t * 17 + q + 2];
        v.w = s[t * 17 + q + 3];
        *(ushort4*)&hist[(long)t * WC + w0 + q] = v;
    }
}

// ---------------- streaming outputs + fused scalars ----------------
template <bool VEC4>
__global__ void __launch_bounds__(256) k_vec(const float* __restrict__ feat,
                                             float* __restrict__ out, int N, int TILE) {
    int warp = threadIdx.x >> 5;
    int lane = threadIdx.x & 31;
    int tok = blockIdx.x * (blockDim.x >> 5) + warp;
    if (tok >= N) return;
    long Nl = N;

    int w0 = g_win0[tok], w1 = g_win1[tok];
    int c0 = w0 >> 1, c1 = w1 >> 1;
    int r0 = g_rank0[tok];
    int lvl0, t0;
    level_target(g_counts0[c0], lvl0, t0);
    bool keep1 = r0 < t0;
    int dl1 = -1, r1o = -1;
    bool keepF = false;
    if (keep1) {
        int t = tok / TILE;
        int r1 = g_rank1[tok] + (int)g_h1[(long)t * WC + c1];
        int lvl, tg;
        level_target(g_counts1[c1], lvl, tg);
        dl1 = lvl;
        r1o = r1;
        keepF = r1 < tg;
    }
    if (lane < 7) {
        float sv;
        switch (lane) {
            case 0: sv = keepF ? 1.0f : 0.0f; break;
            case 1: sv = (float)w0; break;
            case 2: sv = (float)w1; break;
            case 3: sv = (float)lvl0; break;
            case 4: sv = (float)dl1; break;
            case 5: sv = (float)r0; break;
            default: sv = (float)r1o; break;
        }
        __stcs(&out[(long)(128 + lane) * Nl + tok], sv);
    }

    unsigned cw = g_cw[tok];
    int half = lane >> 4;  // 0: x-half (cols 0..63), 1: y-half (64..127)
    int v0 = half ? ((cw >> 8) & 255) : (cw & 255);
    int v1 = half ? ((cw >> 24) & 255) : ((cw >> 16) & 255);
    bool kf = keepF;

    if (VEC4) {
        int col = lane & 15;
        float4 f = __ldcs(&((const float4*)feat)[(long)tok * 32 + lane]);
        if (!kf) { f.x = 0.f; f.y = 0.f; f.z = 0.f; f.w = 0.f; }
        __stcs(&((float4*)out)[(long)tok * 32 + lane], f);
        const float4* tab4 = (const float4*)g_tab;
        float4 p0 = tab4[v0 * 16 + col];
        float4 p1 = tab4[v1 * 16 + col];
        __stcs(&((float4*)(out + 135 * Nl))[(long)tok * 32 + lane], p0);
        __stcs(&((float4*)(out + 263 * Nl))[(long)tok * 32 + lane], p1);
    } else {
#pragma unroll
        for (int k = 0; k < 4; k++) {
            int c = lane * 4 + k;
            float f = feat[(long)tok * 128 + c];
            out[(long)tok * 128 + c] = kf ? f : 0.f;
            int cc = c & 63;
            out[135 * Nl + (long)tok * 128 + c] = g_tab[v0 * 64 + cc];
            out[263 * Nl + (long)tok * 128 + c] = g_tab[v1 * 64 + cc];
        }
    }
}

// ---------------- launch ----------------
extern "C" void kernel_launch(void* const* d_in, const int* in_sizes, int n_in,
                              void* d_out, int out_size) {
    const float* feat = (const float*)d_in[0];
    const int* coords = (const int*)d_in[1];
    float* out = (float*)d_out;
    int N = in_sizes[1] / 4;
    if (N > MAXN) N = MAXN;
    int TILE = (N + NTIL - 1) / NTIL;
    if (TILE < 32) TILE = 32;
    int T = (N + TILE - 1) / TILE;

    int tilepad = (TILE + 15) & ~15;
    int smem = WC * 2 + tilepad * 2 + tilepad;   // ~14.4KB

    k_rank0<<<T, 256, smem>>>(coords, N, TILE);
    k_scan<0><<<WC / 16, 256>>>(T);
    k_rank1<<<T, 256, smem>>>(N, TILE);
    k_scan<1><<<WC / 16, 256>>>(T);

    int vb = (N + 7) / 8;
    if ((N & 3) == 0) k_vec<true><<<vb, 256>>>(feat, out, N, TILE);
    else              k_vec<false><<<vb, 256>>>(feat, out, N, TILE);
}

// round 10
// speedup vs baseline: 6.4171x; 1.0271x over previous
#include <cuda_runtime.h>
#include <math.h>

// ---------------- problem constants ----------------
// SPARSE_SHAPE=(468,468,1), WINDOW=(12,12,1), BATCH=4
// full id = b*3200 + wx*80 + wy*2 + z ; dataset has z==0 always,
// so compressed counting id = id>>1 = b*1600 + wx*40 + wy in [0, 6400)
#define WC 6400
#define MAXN 310016
#define NT 148           // one rank block (1/SM), 16-warp hierarchical rank
#define MAXT 150
#define TILEMAX 2112     // 148*2112 >= MAXN
#define NWARP 16

// ---------------- static scratch ----------------
__device__ int g_win0[MAXN];
__device__ int g_win1[MAXN];
__device__ int g_rank0[MAXN];    // within-tile rank after k_rank0; finalized in k_rank1
__device__ int g_rank1[MAXN];    // within-tile rank; finalized in k_vec
__device__ unsigned g_cw[MAXN];  // packed coords: x0|y0<<8|x1<<16|y1<<24
__device__ unsigned short g_h0[(long)MAXT * WC];  // tile-major hist/prefix
__device__ unsigned short g_h1[(long)MAXT * WC];
__device__ int g_counts0[WC];
__device__ int g_counts1[WC];
__device__ float g_tab[12 * 64]; // sincos LUT

__device__ __forceinline__ void level_target(int n, int& lvl, int& tgt) {
    if (n < 16)      { lvl = 0; tgt = 16; }
    else if (n < 32) { lvl = 1; tgt = 32; }
    else if (n < 64) { lvl = 2; tgt = 64; }
    else             { lvl = 3; tgt = 144; }
}

// Shared layout (dynamic):
//   u16 cnt[NWARP][WC]   205KB-ish  per-warp private counters -> chunk prefixes
//   u16 swin[TILEMAX]    compressed window id per token
//   u16 srank[TILEMAX]   within-chunk rank
//   u8  skeep[TILEMAX]   (pass 1 only)
#define SMEM_RANK_BYTES (NWARP * WC * 2 + TILEMAX * 2 + TILEMAX * 2 + TILEMAX)

// Hierarchical stable-rank core: 16 warps rank disjoint contiguous chunks into
// private counter rows; combine pass makes rows exclusive-over-chunks and emits
// the tile histogram; fixup adds chunk prefix to within-chunk ranks.
template <int PASS>
__device__ __forceinline__ void rank_core(
    unsigned short* cnt, unsigned short* swin, unsigned short* srank,
    const unsigned char* skeep, int* grank, unsigned short* hrow,
    int start, int len, int tid)
{
    int warp = tid >> 5, lane = tid & 31;
    int CH = (len + NWARP - 1) >> 4;            // per-warp chunk length
    if (CH < 1) CH = 1;

    // zero the counters
    for (int j = tid; j < NWARP * WC / 2; j += 512) ((unsigned*)cnt)[j] = 0;
    __syncthreads();

    // per-warp ordered walk over its chunk
    {
        unsigned short* mycnt = cnt + warp * WC;
        int clo = warp * CH;
        int chi = min(clo + CH, len);
        for (int base = clo; base < chi; base += 32) {
            int j = base + lane;
            bool inb = j < chi;
            bool valid = inb && (PASS == 0 || skeep[j]);
            int w = valid ? (int)swin[j] : (WC + lane);
            unsigned peers = __match_any_sync(0xffffffffu, w);
            int leader = __ffs(peers) - 1;
            int r = __popc(peers & ((1u << lane) - 1u));
            int basec = 0;
            if (valid && lane == leader) {
                basec = (int)mycnt[w];
                mycnt[w] = (unsigned short)(basec + __popc(peers));
            }
            basec = __shfl_sync(0xffffffffu, basec, leader);
            if (inb) srank[j] = (unsigned short)(valid ? (basec + r) : 0);
            __syncwarp();
        }
    }
    __syncthreads();

    // combine: exclusive prefix along chunks for each window + histogram out
    for (int w = tid; w < WC; w += 512) {
        int run = 0;
#pragma unroll
        for (int W = 0; W < NWARP; W++) {
            int v = (int)cnt[W * WC + w];
            cnt[W * WC + w] = (unsigned short)run;
            run += v;
        }
        hrow[w] = (unsigned short)run;
    }
    __syncthreads();

    // fixup: within-tile rank = within-chunk + chunk prefix
    for (int j = tid; j < len; j += 512) {
        int W = j / CH;
        grank[start + j] = (int)srank[j] + (int)cnt[W * WC + (int)swin[j]];
    }
}

// ---------------- pass 0: prepare + hierarchical rank + tile histogram ----------------
__global__ void __launch_bounds__(512) k_rank0(const int* __restrict__ coords, int N, int TILE) {
    extern __shared__ unsigned short sh16[];
    unsigned short* cnt = sh16;
    unsigned short* swin = sh16 + NWARP * WC;
    unsigned short* srank = swin + TILEMAX;
    int t = blockIdx.x, tid = threadIdx.x;
    int start = t * TILE;
    int len = min(TILE, N - start);
    if (len < 0) len = 0;

    // sincos LUT, built by block 0
    if (t == 0 && tid < 384) {
        int v = tid >> 5, fi = tid & 31;
        float inv = exp2f((float)fi * 0.41524101186092029f);  // 10000^(fi/32)
        float arg = (float)(v - 6) / inv;
        float s, c;
        sincosf(arg, &s, &c);
        g_tab[v * 64 + 2 * fi]     = s;
        g_tab[v * 64 + 2 * fi + 1] = c;
    }

    for (int j = tid; j < len; j += 512) {
        int i = start + j;
        int4 c4 = ((const int4*)coords)[i];     // (b, z, y, x)
        int b = c4.x, z = c4.y, y = c4.z, x = c4.w;
        int cx0 = x + 12, cy0 = y + 12;         // do_shift=False (sz=0)
        int cx1 = x + 6,  cy1 = y + 6;          // do_shift=True  (sz=0)
        int w0 = b * 3200 + (cx0 / 12) * 80 + (cy0 / 12) * 2 + z;
        int w1 = b * 3200 + (cx1 / 12) * 80 + (cy1 / 12) * 2 + z;
        g_win0[i] = w0;
        g_win1[i] = w1;
        g_cw[i] = (unsigned)(cx0 % 12) | ((unsigned)(cy0 % 12) << 8) |
                  ((unsigned)(cx1 % 12) << 16) | ((unsigned)(cy1 % 12) << 24);
        swin[j] = (unsigned short)(w0 >> 1);    // compressed (z==0)
    }
    __syncthreads();

    rank_core<0>(cnt, swin, srank, (const unsigned char*)0,
                 g_rank0, g_h0 + (long)t * WC, start, len, tid);
}

// ---------------- pass 1: finalize rank0/keep + rank among kept in win1 ----------------
__global__ void __launch_bounds__(512) k_rank1(int N, int TILE) {
    extern __shared__ unsigned short sh16[];
    unsigned short* cnt = sh16;
    unsigned short* swin = sh16 + NWARP * WC;
    unsigned short* srank = swin + TILEMAX;
    unsigned char* skeep = (unsigned char*)(srank + TILEMAX);
    int t = blockIdx.x, tid = threadIdx.x;
    int start = t * TILE;
    int len = min(TILE, N - start);
    if (len < 0) len = 0;
    const unsigned short* pref0 = g_h0 + (long)t * WC;

    for (int j = tid; j < len; j += 512) {
        int i = start + j;
        int c0 = g_win0[i] >> 1;
        int r0 = g_rank0[i] + (int)__ldg(&pref0[c0]);   // finalize pass-0 rank
        g_rank0[i] = r0;
        int lvl, tgt;
        level_target(g_counts0[c0], lvl, tgt);
        skeep[j] = (r0 < tgt) ? 1 : 0;
        swin[j] = (unsigned short)(g_win1[i] >> 1);
    }
    __syncthreads();

    rank_core<1>(cnt, swin, srank, skeep,
                 g_rank1, g_h1 + (long)t * WC, start, len, tid);
}

// ---------------- parallel per-window exclusive scan over tiles ----------------
// 16 windows per block (400 blocks); 32B-sector-aligned ushort4 accesses;
// 16-lane segmented shfl scan, chunk ~10 tiles per lane at T=148.
template <int PASS>
__global__ void __launch_bounds__(256) k_scan(int T) {
    __shared__ unsigned short s[MAXT * 17];
    unsigned short* hist = (PASS == 0) ? g_h0 : g_h1;
    int* counts = (PASS == 0) ? g_counts0 : g_counts1;
    int w0 = blockIdx.x * 16;
    int tid = threadIdx.x;

    int nq = T * 4;
    for (int i = tid; i < nq; i += 256) {
        int t = i >> 2, q = (i & 3) * 4;
        ushort4 v = *(const ushort4*)&hist[(long)t * WC + w0 + q];
        s[t * 17 + q + 0] = v.x;
        s[t * 17 + q + 1] = v.y;
        s[t * 17 + q + 2] = v.z;
        s[t * 17 + q + 3] = v.w;
    }
    __syncthreads();

    int w = tid >> 4, sub = tid & 15;
    int chunk = (T + 15) >> 4;
    int lo = sub * chunk, hi = min(lo + chunk, T);
    int partial = 0;
    for (int t = lo; t < hi; t++) partial += (int)s[t * 17 + w];
    int inc = partial;
#pragma unroll
    for (int d = 1; d < 16; d <<= 1) {
        int v = __shfl_up_sync(0xffffffffu, inc, d, 16);
        if (sub >= d) inc += v;
    }
    int run = inc - partial;
    for (int t = lo; t < hi; t++) {
        int v = (int)s[t * 17 + w];
        s[t * 17 + w] = (unsigned short)run;
        run += v;
    }
    if (sub == 15) counts[w0 + w] = inc;
    __syncthreads();

    for (int i = tid; i < nq; i += 256) {
        int t = i >> 2, q = (i & 3) * 4;
        ushort4 v;
        v.x = s[t * 17 + q + 0];
        v.y = s[t * 17 + q + 1];
        v.z = s[t * 17 + q + 2];
        v.w = s[t * 17 + q + 3];
        *(ushort4*)&hist[(long)t * WC + w0 + q] = v;
    }
}

// ---------------- streaming outputs + fused scalars ----------------
template <bool VEC4>
__global__ void __launch_bounds__(256) k_vec(const float* __restrict__ feat,
                                             float* __restrict__ out, int N, int TILE) {
    int warp = threadIdx.x >> 5;
    int lane = threadIdx.x & 31;
    int tok = blockIdx.x * (blockDim.x >> 5) + warp;
    if (tok >= N) return;
    long Nl = N;

    int w0 = g_win0[tok], w1 = g_win1[tok];
    int c0 = w0 >> 1, c1 = w1 >> 1;
    int r0 = g_rank0[tok];
    int lvl0, t0;
    level_target(g_counts0[c0], lvl0, t0);
    bool keep1 = r0 < t0;
    int dl1 = -1, r1o = -1;
    bool keepF = false;
    if (keep1) {
        int t = tok / TILE;
        int r1 = g_rank1[tok] + (int)g_h1[(long)t * WC + c1];
        int lvl, tg;
        level_target(g_counts1[c1], lvl, tg);
        dl1 = lvl;
        r1o = r1;
        keepF = r1 < tg;
    }
    if (lane < 7) {
        float sv;
        switch (lane) {
            case 0: sv = keepF ? 1.0f : 0.0f; break;
            case 1: sv = (float)w0; break;
            case 2: sv = (float)w1; break;
            case 3: sv = (float)lvl0; break;
            case 4: sv = (float)dl1; break;
            case 5: sv = (float)r0; break;
            default: sv = (float)r1o; break;
        }
        __stcs(&out[(long)(128 + lane) * Nl + tok], sv);
    }

    unsigned cw = g_cw[tok];
    int half = lane >> 4;
    int v0 = half ? ((cw >> 8) & 255) : (cw & 255);
    int v1 = half ? ((cw >> 24) & 255) : ((cw >> 16) & 255);
    bool kf = keepF;

    if (VEC4) {
        int col = lane & 15;
        float4 f = __ldcs(&((const float4*)feat)[(long)tok * 32 + lane]);
        if (!kf) { f.x = 0.f; f.y = 0.f; f.z = 0.f; f.w = 0.f; }
        __stcs(&((float4*)out)[(long)tok * 32 + lane], f);
        const float4* tab4 = (const float4*)g_tab;
        float4 p0 = tab4[v0 * 16 + col];
        float4 p1 = tab4[v1 * 16 + col];
        __stcs(&((float4*)(out + 135 * Nl))[(long)tok * 32 + lane], p0);
        __stcs(&((float4*)(out + 263 * Nl))[(long)tok * 32 + lane], p1);
    } else {
#pragma unroll
        for (int k = 0; k < 4; k++) {
            int c = lane * 4 + k;
            float f = feat[(long)tok * 128 + c];
            out[(long)tok * 128 + c] = kf ? f : 0.f;
            int cc = c & 63;
            out[135 * Nl + (long)tok * 128 + c] = g_tab[v0 * 64 + cc];
            out[263 * Nl + (long)tok * 128 + c] = g_tab[v1 * 64 + cc];
        }
    }
}

// ---------------- launch ----------------
extern "C" void kernel_launch(void* const* d_in, const int* in_sizes, int n_in,
                              void* d_out, int out_size) {
    const float* feat = (const float*)d_in[0];
    const int* coords = (const int*)d_in[1];
    float* out = (float*)d_out;
    int N = in_sizes[1] / 4;
    if (N > MAXN) N = MAXN;
    int TILE = (N + NT - 1) / NT;
    if (TILE < 32) TILE = 32;
    if (TILE > TILEMAX) TILE = TILEMAX;
    int T = (N + TILE - 1) / TILE;

    cudaFuncSetAttribute(k_rank0, cudaFuncAttributeMaxDynamicSharedMemorySize, SMEM_RANK_BYTES);
    cudaFuncSetAttribute(k_rank1, cudaFuncAttributeMaxDynamicSharedMemorySize, SMEM_RANK_BYTES);

    k_rank0<<<T, 512, SMEM_RANK_BYTES>>>(coords, N, TILE);
    k_scan<0><<<WC / 16, 256>>>(T);
    k_rank1<<<T, 512, SMEM_RANK_BYTES>>>(N, TILE);
    k_scan<1><<<WC / 16, 256>>>(T);

    int vb = (N + 7) / 8;
    if ((N & 3) == 0) k_vec<true><<<vb, 256>>>(feat, out, N, TILE);
    else              k_vec<false><<<vb, 256>>>(feat, out, N, TILE);
}